// round 12
// baseline (speedup 1.0000x reference)
#include <cuda_runtime.h>
#include <cuda_bf16.h>

// x (64, 96, 8, 8) fp32 -> out (64, 96, 96, 8, 8, 2) fp32
// out[b,i,j,c1,c2,0] = x[b,i,c1,c2]; out[b,i,j,c1,c2,1] = x[b,j,c1,c2]
//
// 256-bit store version (st.global.v8.f32, sm_100a+).
// Block = (b, i, jt): 128 threads, 4 warps, 32 j's per block.
// Warp w covers j = jt*32 + w*8 + {0..7}:
//   lane = jp*16 + k4 ; jp = lane>>4 picks even/odd j of a pair,
//   k4 = lane&15 picks the float4 within the 64-float source block.
// Per thread: 1 xi LDG.128 (reused) + 4 xj LDG.128 -> 4 independent STG.256.
// Each warp store = 1024B fully contiguous (two adjacent 512B j-blocks).

#define GS  96
#define JT  3             // j-tiles of 32 per (b,i)

__global__ __launch_bounds__(128)
void gcom_kernel(const float* __restrict__ x, float* __restrict__ out)
{
    unsigned blk = blockIdx.x;             // (b*96 + i)*3 + jt
    unsigned jt  = blk % JT;
    unsigned bi  = blk / JT;               // b*96 + i
    unsigned b   = bi / GS;
    unsigned i   = bi - b * GS;

    unsigned lane = threadIdx.x & 31u;
    unsigned w    = threadIdx.x >> 5;      // warp 0..3
    unsigned k4   = lane & 15u;            // float4 index within 64-float block
    unsigned jp   = lane >> 4;             // 0/1: which j of the adjacent pair
    unsigned jw   = jt * 32 + w * 8;       // warp's first j

    const float4* xrow = (const float4*)(x + (size_t)b * GS * 64);

    // Loads hoisted: xi reused across all 8 j's; 4 independent xj loads.
    float4 a = __ldg(xrow + i * 16 + k4);
    const float4* xj = xrow + (jw + jp) * 16 + k4;
    float4 c0 = __ldg(xj);
    float4 c1 = __ldg(xj + 2 * 16);
    float4 c2 = __ldg(xj + 4 * 16);
    float4 c3 = __ldg(xj + 6 * 16);

    // Store base: float offset ((bi*96 + jw + jp) * 128) + k4*8.
    float* o = out + ((size_t)bi * GS + jw + jp) * 128 + k4 * 8;

#define ST8(ptr, A, C)                                                        \
    asm volatile("st.global.v8.f32 [%0], {%1,%2,%3,%4,%5,%6,%7,%8};"          \
                 :: "l"(ptr),                                                 \
                    "f"((A).x), "f"((C).x), "f"((A).y), "f"((C).y),           \
                    "f"((A).z), "f"((C).z), "f"((A).w), "f"((C).w)            \
                 : "memory")

    ST8(o,           a, c0);
    ST8(o + 2 * 128, a, c1);
    ST8(o + 4 * 128, a, c2);
    ST8(o + 6 * 128, a, c3);
#undef ST8
}

extern "C" void kernel_launch(void* const* d_in, const int* in_sizes, int n_in,
                              void* d_out, int out_size)
{
    const float* x = (const float*)d_in[0];
    float* out = (float*)d_out;

    // 64 * 96 * 3 = 18432 blocks; each writes 32 j's x 512B = 16KB of output.
    gcom_kernel<<<64 * GS * JT, 128>>>(x, out);
}

// round 13
// speedup vs baseline: 1.0533x; 1.0533x over previous
#include <cuda_runtime.h>
#include <cuda_bf16.h>

// x (64, 96, 8, 8) fp32 -> out (64, 96, 96, 8, 8, 2) fp32
// out[b,i,j,c1,c2,0] = x[b,i,c1,c2]; out[b,i,j,c1,c2,1] = x[b,j,c1,c2]
//
// Best-known shape (R9): block = (b, i, jt), 128 threads / 4 warps, 16 j's.
//   warp w handles j = jt*16 + w*4 + {0..3}; lane = k2 (0..31).
// Per thread: 1 xi float2 load (reused) + 4 independent xj loads
//             -> 4 independent 512B-coalesced float4 stores.
// Single change vs R9: __stcs (evict-first) on the stores — output lines are
// never re-read, so keep them out of L2's working set and start writeback early.

#define GS  96
#define BLK 64            // 8*8 floats per group block
#define F4  32            // float4 per (b,i,j) pair
#define JT  6             // j-tiles per (b,i): 6 * 16 = 96

__global__ __launch_bounds__(128)
void gcom_kernel(const float* __restrict__ x, float4* __restrict__ out)
{
    unsigned blk = blockIdx.x;             // (b*96 + i)*6 + jt
    unsigned jt  = blk % JT;
    unsigned bi  = blk / JT;               // b*96 + i
    unsigned b   = bi / GS;
    unsigned i   = bi - b * GS;

    unsigned lane = threadIdx.x & 31u;     // k2: float2 index within 64-float block
    unsigned w    = threadIdx.x >> 5;      // warp 0..3
    unsigned j0   = jt * 16 + w * 4;       // first of 4 j's for this warp

    const float2* xrow = (const float2*)(x + (size_t)b * GS * BLK);

    // All loads issued up front (independent; xi reused for 4 stores).
    float2 a  = __ldg(xrow + i * F4 + lane);
    const float2* xj = xrow + j0 * F4 + lane;
    float2 c0 = __ldg(xj);
    float2 c1 = __ldg(xj + F4);
    float2 c2 = __ldg(xj + 2 * F4);
    float2 c3 = __ldg(xj + 3 * F4);

    float4* o = out + ((size_t)bi * GS + j0) * F4 + lane;
    __stcs(o,          make_float4(a.x, c0.x, a.y, c0.y));
    __stcs(o + F4,     make_float4(a.x, c1.x, a.y, c1.y));
    __stcs(o + 2 * F4, make_float4(a.x, c2.x, a.y, c2.y));
    __stcs(o + 3 * F4, make_float4(a.x, c3.x, a.y, c3.y));
}

extern "C" void kernel_launch(void* const* d_in, const int* in_sizes, int n_in,
                              void* d_out, int out_size)
{
    const float* x = (const float*)d_in[0];
    float4* out = (float4*)d_out;

    // 64 * 96 * 6 = 36864 blocks; each writes 16 * 512B = 8KB of output.
    gcom_kernel<<<64 * GS * JT, 128>>>(x, out);
}